// round 5
// baseline (speedup 1.0000x reference)
#include <cuda_runtime.h>

// Problem constants
#define Bn   4
#define CHI  256
#define CHO  256
#define Hd   96
#define Wd   96
#define Kt   9
#define HW   (Hd*Wd)          // 9216
#define Mpx  (Bn*HW)          // 36864
#define KD   (CHI*Kt)         // 2304
#define BN_EPS 1e-5f

// Bilinear tap: 4 clamped offsets + 4 corner weights (validity+mask folded in)
struct __align__(16) TapParam {
    int   o00, o01, o10, o11;
    float w00, w01, w10, w11;
};

// Scratch (device globals: allocation-guard-safe)
__device__ TapParam       g_params[Bn * Kt * HW];                  // ~10.6 MB
__device__ __align__(16) unsigned short g_wh[(size_t)CHO * KD];    // 1.18 MB
__device__ __align__(16) unsigned short g_wl[(size_t)CHO * KD];
__device__ float          g_stats[2 * CHO];

// bf16 round-to-nearest-even helper
__device__ __forceinline__ unsigned bf16_rn(float v) {
    unsigned u = __float_as_uint(v);
    return (u + 0x7FFFu + ((u >> 16) & 1u)) >> 16;
}

// ---------------------------------------------------------------------------
// Kernel 1: offset conv (256->27, 3x3, pad 1) -> TapParams.
// ---------------------------------------------------------------------------
#define OC  27
#define OCP 32

__global__ void __launch_bounds__(128) k_offset(
    const float* __restrict__ x,
    const float* __restrict__ w_off,
    const float* __restrict__ b_off)
{
    __shared__ float ws[32 * 9 * OCP];
    int p  = blockIdx.x * 128 + threadIdx.x;
    int b  = p / HW, hw = p % HW;
    int h  = hw / Wd, w = hw % Wd;

    float acc[OC];
#pragma unroll
    for (int i = 0; i < OC; i++) acc[i] = 0.f;

    for (int c0 = 0; c0 < CHI; c0 += 32) {
        __syncthreads();
        for (int i = threadIdx.x; i < 32 * 9 * OC; i += 128) {
            int oc = i % OC;
            int ct = i / OC;
            ws[ct * OCP + oc] = w_off[(oc * CHI + c0 + ct / 9) * 9 + (ct % 9)];
        }
        __syncthreads();

        const float* xb = x + ((size_t)b * CHI + c0) * HW;
        for (int cc = 0; cc < 32; cc++) {
            const float* xc = xb + cc * HW;
#pragma unroll
            for (int ty = 0; ty < 3; ty++) {
                int y = h + ty - 1;
                bool yv = ((unsigned)y < (unsigned)Hd);
#pragma unroll
                for (int tx = 0; tx < 3; tx++) {
                    int xx = w + tx - 1;
                    float xv = (yv && (unsigned)xx < (unsigned)Wd) ? xc[y * Wd + xx] : 0.f;
                    const float* wr = &ws[(cc * 9 + ty * 3 + tx) * OCP];
#pragma unroll
                    for (int oc = 0; oc < OC; oc++) acc[oc] += wr[oc] * xv;
                }
            }
        }
    }

#pragma unroll
    for (int k = 0; k < Kt; k++) {
        float dy = acc[2 * k]     + b_off[2 * k];
        float dx = acc[2 * k + 1] + b_off[2 * k + 1];
        float mz = acc[18 + k]    + b_off[18 + k];
        float m  = 1.f / (1.f + expf(-mz));

        float py = dy + (float)(h + k / 3 - 1);
        float px = dx + (float)(w + k % 3 - 1);
        float fy = floorf(py), fx = floorf(px);
        float ly = py - fy,    lx = px - fx;
        int y0 = (int)fy, x0 = (int)fx, y1 = y0 + 1, x1 = x0 + 1;

        float vy0 = ((unsigned)y0 < (unsigned)Hd) ? 1.f : 0.f;
        float vy1 = ((unsigned)y1 < (unsigned)Hd) ? 1.f : 0.f;
        float vx0 = ((unsigned)x0 < (unsigned)Wd) ? 1.f : 0.f;
        float vx1 = ((unsigned)x1 < (unsigned)Wd) ? 1.f : 0.f;

        int y0c = min(max(y0, 0), Hd - 1), y1c = min(max(y1, 0), Hd - 1);
        int x0c = min(max(x0, 0), Wd - 1), x1c = min(max(x1, 0), Wd - 1);

        TapParam tp;
        tp.o00 = y0c * Wd + x0c;  tp.o01 = y0c * Wd + x1c;
        tp.o10 = y1c * Wd + x0c;  tp.o11 = y1c * Wd + x1c;
        tp.w00 = (1.f - ly) * (1.f - lx) * vy0 * vx0 * m;
        tp.w01 = (1.f - ly) * lx         * vy0 * vx1 * m;
        tp.w10 = ly * (1.f - lx)         * vy1 * vx0 * m;
        tp.w11 = ly * lx                 * vy1 * vx1 * m;
        g_params[(b * Kt + k) * HW + hw] = tp;
    }
}

// ---------------------------------------------------------------------------
// Kernel 2: split w_conv into bf16 hi/lo, [CHO][KD] K-major.
// ---------------------------------------------------------------------------
__global__ void __launch_bounds__(256) k_wsplit(const float* __restrict__ w)
{
    int i = blockIdx.x * 256 + threadIdx.x;
    float v = w[i];
    unsigned hb = bf16_rn(v);
    float r = v - __uint_as_float(hb << 16);
    g_wh[i] = (unsigned short)hb;
    g_wl[i] = (unsigned short)bf16_rn(r);
}

// ---------------------------------------------------------------------------
// Kernel 3: FUSED deformable-gather + mma.sync bf16 GEMM.
// CTA: 128 CHO x 128 pixels, 8 warps (warp tile 64x32), BK=64, 2 stages.
// B tile (cols) is built in-kernel: gather from x + split-bf16 + swizzled STS.
// A tile (weights) via cp.async. smem: 2*(Ah,Al,Bh,Bl) + tap params.
// ---------------------------------------------------------------------------
#define NCHUNK 36
#define TILEB  16384                 // 128 rows x 128 bytes
#define STAGEB (4 * TILEB)           // Ahi Alo Bhi Blo
#define PARAM_OFF (2 * STAGEB)       // 131072
#define PHALF  (9 * 128 * 16)        // 18432: int4 block, then float4 block
#define SMEMSZ (PARAM_OFF + 2 * PHALF)

#define LDM4(R0,R1,R2,R3,ADDR) \
    asm volatile("ldmatrix.sync.aligned.m8n8.x4.shared.b16 {%0,%1,%2,%3}, [%4];" \
                 : "=r"(R0),"=r"(R1),"=r"(R2),"=r"(R3) : "r"(ADDR))

#define MMA(C,A,B0,B1) \
    asm volatile("mma.sync.aligned.m16n8k16.row.col.f32.bf16.bf16.f32 " \
                 "{%0,%1,%2,%3},{%4,%5,%6,%7},{%8,%9},{%0,%1,%2,%3};" \
                 : "+f"((C)[0]),"+f"((C)[1]),"+f"((C)[2]),"+f"((C)[3]) \
                 : "r"((A)[0]),"r"((A)[1]),"r"((A)[2]),"r"((A)[3]),   \
                   "r"(B0),"r"(B1))

__device__ __forceinline__ void loadA(unsigned smBase, int stage, int chunk,
                                      int oBase, int tid)
{
    int k0 = chunk * 64;
#pragma unroll
    for (int j = 0; j < 8; j++) {
        int i    = tid + j * 256;        // 0..2047
        int tile = i >> 10;              // 0..1
        int row  = (i >> 3) & 127;
        int u    = i & 7;
        const unsigned short* src = tile ? g_wl : g_wh;
        const char* g = (const char*)src + ((size_t)(oBase + row) * KD + k0) * 2 + u * 16;
        unsigned d = smBase + stage * STAGEB + tile * TILEB + row * 128
                   + ((u ^ (row & 7)) * 16);
        asm volatile("cp.async.cg.shared.global [%0], [%1], 16;" :: "r"(d), "l"(g));
    }
    asm volatile("cp.async.commit_group;" ::: "memory");
}

// Build B tile for one chunk: 128 px x 64 kd, bf16 hi/lo, swizzled smem rows.
__device__ __forceinline__ void buildB(char* sm, int stage, int chunk,
                                       const float* __restrict__ xb, int tid)
{
    const int4*   spo = (const int4*)(sm + PARAM_OFF);
    const float4* spw = (const float4*)(sm + PARAM_OFF + PHALF);
    int px = tid & 127;
    int e0 = (tid >> 7) * 32;
    int kd = chunk * 64 + e0;
    int c  = kd / 9;
    int tap = kd - c * 9;
    const float* xp = xb + (size_t)c * HW;
    char* rowH = sm + stage * STAGEB + 2 * TILEB + px * 128;
    char* rowL = rowH + TILEB;
    unsigned swm = px & 7;
    unsigned hp = 0, lp = 0;
#pragma unroll 8
    for (int i = 0; i < 32; i++) {
        int e = e0 + i;
        int4   o  = spo[tap * 128 + px];
        float4 wv = spw[tap * 128 + px];
        float v = wv.x * __ldg(xp + o.x) + wv.y * __ldg(xp + o.y)
                + wv.z * __ldg(xp + o.z) + wv.w * __ldg(xp + o.w);
        unsigned hb = bf16_rn(v);
        float r = v - __uint_as_float(hb << 16);
        unsigned lb = bf16_rn(r);
        if ((i & 1) == 0) { hp = hb; lp = lb; }
        else {
            hp |= hb << 16; lp |= lb << 16;
            unsigned off = (((e >> 3) ^ swm) * 16) + ((e & 6) * 2);
            *(unsigned*)(rowH + off) = hp;
            *(unsigned*)(rowL + off) = lp;
        }
        if (++tap == 9) { tap = 0; xp += HW; }
    }
}

__global__ void __launch_bounds__(256, 1) k_gemm(
    const float* __restrict__ bconv,
    const float* __restrict__ x,
    float* __restrict__ out)
{
    extern __shared__ char sm[];
    unsigned smBase = (unsigned)__cvta_generic_to_shared(sm);

    int tid = threadIdx.x, lane = tid & 31, wid = tid >> 5;
    int wm = wid & 1;            // m half (64 rows)
    int wn = wid >> 1;           // n quarter (32 pixels)
    int pBase = blockIdx.x * 128;
    int oBase = blockIdx.y * 128;
    int b = pBase / HW, hwB = pBase % HW;
    const float* xb = x + (size_t)b * CHI * HW;

    // Stage tap params for this CTA's 128 pixels: [tap][px] int4 + float4.
    {
        int4*   spo = (int4*)(sm + PARAM_OFF);
        float4* spw = (float4*)(sm + PARAM_OFF + PHALF);
        for (int t = tid; t < 9 * 128; t += 256) {
            int tap = t >> 7, px = t & 127;
            const uint4* gp = (const uint4*)&g_params[(b * Kt + tap) * HW + hwB + px];
            ((uint4*)spo)[t] = gp[0];
            ((uint4*)spw)[t] = gp[1];
        }
    }

    // ldmatrix per-lane geometry
    unsigned aRL = ((lane >> 3) & 1) * 8 + (lane & 7);
    unsigned aU  = lane >> 4;
    unsigned bRL = ((lane >> 4) & 1) * 8 + (lane & 7);
    unsigned bU  = (lane >> 3) & 1;
    unsigned aRowOff[4], bRowOff[2];
#pragma unroll
    for (int mt = 0; mt < 4; mt++) aRowOff[mt] = (wm * 64 + mt * 16 + aRL) * 128;
#pragma unroll
    for (int nt = 0; nt < 2; nt++) bRowOff[nt] = (wn * 32 + nt * 16 + bRL) * 128;
    unsigned aMsk = aRL & 7, bMsk = bRL & 7;

    float c[16][4];
#pragma unroll
    for (int i = 0; i < 16; i++)
#pragma unroll
        for (int j = 0; j < 4; j++) c[i][j] = 0.f;

    __syncthreads();                       // params visible
    loadA(smBase, 0, 0, oBase, tid);
    buildB(sm, 0, 0, xb, tid);

    for (int ch = 0; ch < NCHUNK; ch++) {
        int st = ch & 1;
        if (ch + 1 < NCHUNK) {
            loadA(smBase, st ^ 1, ch + 1, oBase, tid);
            buildB(sm, st ^ 1, ch + 1, xb, tid);
            asm volatile("cp.async.wait_group 1;" ::: "memory");
        } else {
            asm volatile("cp.async.wait_group 0;" ::: "memory");
        }
        __syncthreads();

        unsigned base = smBase + st * STAGEB;
        unsigned sAh = base, sAl = base + TILEB;
        unsigned sBh = base + 2 * TILEB, sBl = base + 3 * TILEB;

#pragma unroll
        for (int kk = 0; kk < 4; kk++) {
            unsigned ua = ((kk * 2 + aU) ^ aMsk) * 16;
            unsigned ub = ((kk * 2 + bU) ^ bMsk) * 16;

            unsigned ah[4][4], al[4][4], bh[2][4], bl[2][4];
#pragma unroll
            for (int mt = 0; mt < 4; mt++) {
                LDM4(ah[mt][0], ah[mt][1], ah[mt][2], ah[mt][3], sAh + aRowOff[mt] + ua);
                LDM4(al[mt][0], al[mt][1], al[mt][2], al[mt][3], sAl + aRowOff[mt] + ua);
            }
#pragma unroll
            for (int nt = 0; nt < 2; nt++) {
                LDM4(bh[nt][0], bh[nt][1], bh[nt][2], bh[nt][3], sBh + bRowOff[nt] + ub);
                LDM4(bl[nt][0], bl[nt][1], bl[nt][2], bl[nt][3], sBl + bRowOff[nt] + ub);
            }

#pragma unroll
            for (int mt = 0; mt < 4; mt++)
#pragma unroll
                for (int nt = 0; nt < 4; nt++) {
                    int n2 = nt >> 1, jj = (nt & 1) * 2;
                    float* cc = c[mt * 4 + nt];
                    MMA(cc, ah[mt], bh[n2][jj], bh[n2][jj + 1]);
                    MMA(cc, ah[mt], bl[n2][jj], bl[n2][jj + 1]);
                    MMA(cc, al[mt], bh[n2][jj], bh[n2][jj + 1]);
                }
        }
        __syncthreads();
    }

    // Epilogue: + bias, NCHW stores.
#pragma unroll
    for (int mt = 0; mt < 4; mt++) {
        int o = oBase + wm * 64 + mt * 16 + (lane >> 2);
        float bias0 = bconv[o], bias8 = bconv[o + 8];
        float* r0p = out + ((size_t)b * CHO + o) * HW + hwB;
        float* r8p = r0p + 8 * HW;
#pragma unroll
        for (int nt = 0; nt < 4; nt++) {
            int p = wn * 32 + nt * 8 + (lane & 3) * 2;
            float2 v0 = make_float2(c[mt * 4 + nt][0] + bias0, c[mt * 4 + nt][1] + bias0);
            float2 v1 = make_float2(c[mt * 4 + nt][2] + bias8, c[mt * 4 + nt][3] + bias8);
            *(float2*)(r0p + p) = v0;
            *(float2*)(r8p + p) = v1;
        }
    }
}

// ---------------------------------------------------------------------------
// Kernel 4/5: BN stats + apply.
// ---------------------------------------------------------------------------
__global__ void __launch_bounds__(256) k_bnstats(const float* __restrict__ out)
{
    __shared__ float ss[256], ss2[256];
    int o = blockIdx.x;
    float s = 0.f, s2 = 0.f;
    for (int i = threadIdx.x; i < Bn * HW; i += 256) {
        int b = i / HW;
        float v = out[((size_t)b * CHO + o) * HW + (i % HW)];
        s += v; s2 += v * v;
    }
    ss[threadIdx.x] = s; ss2[threadIdx.x] = s2;
    __syncthreads();
    for (int st = 128; st > 0; st >>= 1) {
        if (threadIdx.x < st) {
            ss[threadIdx.x]  += ss[threadIdx.x + st];
            ss2[threadIdx.x] += ss2[threadIdx.x + st];
        }
        __syncthreads();
    }
    if (threadIdx.x == 0) {
        float inv_n = 1.f / (float)(Bn * HW);
        float mean = ss[0] * inv_n;
        float var  = ss2[0] * inv_n - mean * mean;
        g_stats[o]       = mean;
        g_stats[CHO + o] = rsqrtf(var + BN_EPS);
    }
}

__global__ void __launch_bounds__(256) k_bnapply(
    float* __restrict__ out,
    const float* __restrict__ gamma,
    const float* __restrict__ beta)
{
    int i = blockIdx.x * 256 + threadIdx.x;
    int o = (i / HW) & (CHO - 1);
    float v = out[i];
    float y = gamma[o] * ((v - g_stats[o]) * g_stats[CHO + o]) + beta[o];
    out[i] = fmaxf(y, 0.f);
}

// ---------------------------------------------------------------------------
extern "C" void kernel_launch(void* const* d_in, const int* in_sizes, int n_in,
                              void* d_out, int out_size)
{
    const float* x      = (const float*)d_in[0];
    const float* w_off  = (const float*)d_in[1];
    const float* b_off  = (const float*)d_in[2];
    const float* w_conv = (const float*)d_in[3];
    const float* b_conv = (const float*)d_in[4];
    const float* gamma  = (const float*)d_in[5];
    const float* beta   = (const float*)d_in[6];
    float* out = (float*)d_out;

    cudaFuncSetAttribute(k_gemm, cudaFuncAttributeMaxDynamicSharedMemorySize,
                         SMEMSZ);

    k_offset<<<Mpx / 128, 128>>>(x, w_off, b_off);
    k_wsplit<<<(CHO * KD) / 256, 256>>>(w_conv);

    dim3 ggemm(Mpx / 128, CHO / 128);
    k_gemm<<<ggemm, 256, SMEMSZ>>>(b_conv, x, out);

    k_bnstats<<<CHO, 256>>>(out);
    k_bnapply<<<(size_t)Bn * CHO * HW / 256, 256>>>(out, gamma, beta);
}

// round 8
// speedup vs baseline: 1.3133x; 1.3133x over previous
#include <cuda_runtime.h>

// Problem constants
#define Bn   4
#define CHI  256
#define CHO  256
#define Hd   96
#define Wd   96
#define Kt   9
#define HW   (Hd*Wd)          // 9216
#define Mpx  (Bn*HW)          // 36864
#define KD   (CHI*Kt)         // 2304
#define BN_EPS 1e-5f

// Bilinear tap: 4 clamped offsets + 4 corner weights (validity+mask folded in)
struct __align__(16) TapParam {
    int   o00, o01, o10, o11;
    float w00, w01, w10, w11;
};

// Scratch (device globals: allocation-guard-safe)
__device__ TapParam       g_params[Bn * Kt * HW];                       // ~10.6 MB
__device__ __align__(16) unsigned short g_colsh[(size_t)Mpx * KD];      // 170 MB
__device__ __align__(16) unsigned short g_colsl[(size_t)Mpx * KD];      // 170 MB
__device__ __align__(16) unsigned short g_wh[(size_t)CHO * KD];         // 1.18 MB
__device__ __align__(16) unsigned short g_wl[(size_t)CHO * KD];
__device__ float          g_stats[2 * CHO];

// bf16 round-to-nearest-even helper
__device__ __forceinline__ unsigned bf16_rn(float v) {
    unsigned u = __float_as_uint(v);
    return (u + 0x7FFFu + ((u >> 16) & 1u)) >> 16;
}

// ---------------------------------------------------------------------------
// Kernel 1: offset conv (256->27, 3x3, pad 1) -> TapParams.
// Weights staged in smem, read as float4 (7 LDS.128 per tap instead of 27 LDS).
// ---------------------------------------------------------------------------
#define OC  27
#define OCP 32

__global__ void __launch_bounds__(128) k_offset(
    const float* __restrict__ x,
    const float* __restrict__ w_off,
    const float* __restrict__ b_off)
{
    __shared__ float ws[32 * 9 * OCP];
    int p  = blockIdx.x * 128 + threadIdx.x;
    int b  = p / HW, hw = p % HW;
    int h  = hw / Wd, w = hw % Wd;

    float acc[28];
#pragma unroll
    for (int i = 0; i < 28; i++) acc[i] = 0.f;

    for (int c0 = 0; c0 < CHI; c0 += 32) {
        __syncthreads();
        for (int i = threadIdx.x; i < 32 * 9 * OC; i += 128) {
            int oc = i % OC;
            int ct = i / OC;
            ws[ct * OCP + oc] = w_off[(oc * CHI + c0 + ct / 9) * 9 + (ct % 9)];
        }
        __syncthreads();

        const float* xb = x + ((size_t)b * CHI + c0) * HW;
        for (int cc = 0; cc < 32; cc++) {
            const float* xc = xb + cc * HW;
            float xv[9];
#pragma unroll
            for (int ty = 0; ty < 3; ty++) {
                int y = h + ty - 1;
                bool yv = ((unsigned)y < (unsigned)Hd);
#pragma unroll
                for (int tx = 0; tx < 3; tx++) {
                    int xx = w + tx - 1;
                    xv[ty * 3 + tx] =
                        (yv && (unsigned)xx < (unsigned)Wd) ? xc[y * Wd + xx] : 0.f;
                }
            }
#pragma unroll
            for (int t = 0; t < 9; t++) {
                const float4* wr4 = (const float4*)&ws[(cc * 9 + t) * OCP];
                float xvt = xv[t];
#pragma unroll
                for (int j = 0; j < 7; j++) {
                    float4 w4 = wr4[j];
                    acc[j * 4 + 0] += w4.x * xvt;
                    acc[j * 4 + 1] += w4.y * xvt;
                    acc[j * 4 + 2] += w4.z * xvt;
                    acc[j * 4 + 3] += w4.w * xvt;
                }
            }
        }
    }

#pragma unroll
    for (int k = 0; k < Kt; k++) {
        float dy = acc[2 * k]     + b_off[2 * k];
        float dx = acc[2 * k + 1] + b_off[2 * k + 1];
        float mz = acc[18 + k]    + b_off[18 + k];
        float m  = 1.f / (1.f + expf(-mz));

        float py = dy + (float)(h + k / 3 - 1);
        float px = dx + (float)(w + k % 3 - 1);
        float fy = floorf(py), fx = floorf(px);
        float ly = py - fy,    lx = px - fx;
        int y0 = (int)fy, x0 = (int)fx, y1 = y0 + 1, x1 = x0 + 1;

        float vy0 = ((unsigned)y0 < (unsigned)Hd) ? 1.f : 0.f;
        float vy1 = ((unsigned)y1 < (unsigned)Hd) ? 1.f : 0.f;
        float vx0 = ((unsigned)x0 < (unsigned)Wd) ? 1.f : 0.f;
        float vx1 = ((unsigned)x1 < (unsigned)Wd) ? 1.f : 0.f;

        int y0c = min(max(y0, 0), Hd - 1), y1c = min(max(y1, 0), Hd - 1);
        int x0c = min(max(x0, 0), Wd - 1), x1c = min(max(x1, 0), Wd - 1);

        TapParam tp;
        tp.o00 = y0c * Wd + x0c;  tp.o01 = y0c * Wd + x1c;
        tp.o10 = y1c * Wd + x0c;  tp.o11 = y1c * Wd + x1c;
        tp.w00 = (1.f - ly) * (1.f - lx) * vy0 * vx0 * m;
        tp.w01 = (1.f - ly) * lx         * vy0 * vx1 * m;
        tp.w10 = ly * (1.f - lx)         * vy1 * vx0 * m;
        tp.w11 = ly * lx                 * vy1 * vx1 * m;
        g_params[(b * Kt + k) * HW + hw] = tp;
    }
}

// ---------------------------------------------------------------------------
// Kernel 2: split w_conv into bf16 hi/lo, [CHO][KD] K-major.
// ---------------------------------------------------------------------------
__global__ void __launch_bounds__(256) k_wsplit(const float* __restrict__ w)
{
    int i = blockIdx.x * 256 + threadIdx.x;
    float v = w[i];
    unsigned hb = bf16_rn(v);
    float r = v - __uint_as_float(hb << 16);
    g_wh[i] = (unsigned short)hb;
    g_wl[i] = (unsigned short)bf16_rn(r);
}

// ---------------------------------------------------------------------------
// Kernel 3: deformable im2col -> bf16 hi/lo, K-major [pixel][KD].
// Thread = pixel; 9 TapParams held in registers; all 32 channel-chunks inside.
// ---------------------------------------------------------------------------
__global__ void __launch_bounds__(128) k_cols(const float* __restrict__ x)
{
    int p  = blockIdx.x * 128 + threadIdx.x;   // grid.x = 288
    int b  = p / HW, hw = p % HW;
    const float* xbase = x + (size_t)b * CHI * HW;

    TapParam tp[9];
#pragma unroll
    for (int k = 0; k < Kt; k++) tp[k] = g_params[(b * Kt + k) * HW + hw];

    for (int c0 = 0; c0 < CHI; c0 += 8) {
        const float* xb = xbase + (size_t)c0 * HW;
        unsigned hbuf[36], lbuf[36];
#pragma unroll
        for (int j = 0; j < 36; j++) { hbuf[j] = 0u; lbuf[j] = 0u; }

#pragma unroll
        for (int k = 0; k < Kt; k++) {
#pragma unroll
            for (int cc = 0; cc < 8; cc++) {
                const float* xc = xb + cc * HW;
                float v = tp[k].w00 * __ldg(xc + tp[k].o00)
                        + tp[k].w01 * __ldg(xc + tp[k].o01)
                        + tp[k].w10 * __ldg(xc + tp[k].o10)
                        + tp[k].w11 * __ldg(xc + tp[k].o11);
                unsigned hb = bf16_rn(v);
                float r = v - __uint_as_float(hb << 16);
                unsigned lb = bf16_rn(r);
                int e = cc * 9 + k;
                int sh = (e & 1) * 16;
                hbuf[e >> 1] |= hb << sh;
                lbuf[e >> 1] |= lb << sh;
            }
        }

        uint4* dh = (uint4*)(g_colsh + (size_t)p * KD + c0 * 9);
        uint4* dl = (uint4*)(g_colsl + (size_t)p * KD + c0 * 9);
#pragma unroll
        for (int j = 0; j < 9; j++) {
            dh[j] = make_uint4(hbuf[4*j], hbuf[4*j+1], hbuf[4*j+2], hbuf[4*j+3]);
            dl[j] = make_uint4(lbuf[4*j], lbuf[4*j+1], lbuf[4*j+2], lbuf[4*j+3]);
        }
    }
}

// ---------------------------------------------------------------------------
// Kernel 4: mma.sync (HMMA bf16) GEMM, split-bf16 3-product fp32 accumulation.
// CTA: 128 CHO x 128 pixels. 8 warps, warp tile 64x32. BK=64, 2-stage cp.async.
// smem tile: [128 rows][64 bf16] with SW128 row swizzle (u ^= row&7).
// ---------------------------------------------------------------------------
#define NCHUNK 36
#define TILEB  16384                 // 128 rows x 128 bytes
#define STAGEB (4 * TILEB)           // Ahi Alo Bhi Blo

#define LDM4(R0,R1,R2,R3,ADDR) \
    asm volatile("ldmatrix.sync.aligned.m8n8.x4.shared.b16 {%0,%1,%2,%3}, [%4];" \
                 : "=r"(R0),"=r"(R1),"=r"(R2),"=r"(R3) : "r"(ADDR))

#define MMA(C,A,B0,B1) \
    asm volatile("mma.sync.aligned.m16n8k16.row.col.f32.bf16.bf16.f32 " \
                 "{%0,%1,%2,%3},{%4,%5,%6,%7},{%8,%9},{%0,%1,%2,%3};" \
                 : "+f"((C)[0]),"+f"((C)[1]),"+f"((C)[2]),"+f"((C)[3]) \
                 : "r"((A)[0]),"r"((A)[1]),"r"((A)[2]),"r"((A)[3]),   \
                   "r"(B0),"r"(B1))

__device__ __forceinline__ void load_chunk(unsigned smBase, int stage, int chunk,
                                           int oBase, int pBase, int tid)
{
    unsigned dstBase = smBase + stage * STAGEB;
    int k0 = chunk * 64;
#pragma unroll
    for (int j = 0; j < 16; j++) {
        int i    = tid + j * 256;        // 0..4095
        int tile = i >> 10;              // 0..3
        int row  = (i >> 3) & 127;
        int u    = i & 7;
        const unsigned short* src;
        int rbase;
        if (tile < 2) { src = (tile == 0) ? g_wh   : g_wl;   rbase = oBase; }
        else          { src = (tile == 2) ? g_colsh : g_colsl; rbase = pBase; }
        const char* g = (const char*)src + ((size_t)(rbase + row) * KD + k0) * 2 + u * 16;
        unsigned d = dstBase + tile * TILEB + row * 128 + ((u ^ (row & 7)) * 16);
        asm volatile("cp.async.cg.shared.global [%0], [%1], 16;" :: "r"(d), "l"(g));
    }
    asm volatile("cp.async.commit_group;" ::: "memory");
}

__global__ void __launch_bounds__(256, 1) k_gemm(
    const float* __restrict__ bconv,
    float* __restrict__ out)
{
    extern __shared__ char sm[];
    unsigned smBase = (unsigned)__cvta_generic_to_shared(sm);

    int tid = threadIdx.x, lane = tid & 31, wid = tid >> 5;
    int wm = wid & 1;            // m half (64 rows)
    int wn = wid >> 1;           // n quarter (32 pixels)
    int pBase = blockIdx.x * 128;
    int oBase = blockIdx.y * 128;

    // ldmatrix per-lane geometry
    unsigned aRL = ((lane >> 3) & 1) * 8 + (lane & 7);   // A: row-in-tile16
    unsigned aU  = lane >> 4;                            // A: k8 unit
    unsigned bRL = ((lane >> 4) & 1) * 8 + (lane & 7);   // B: row-in-tile16
    unsigned bU  = (lane >> 3) & 1;                      // B: k8 unit
    unsigned aRowOff[4], bRowOff[2];
#pragma unroll
    for (int mt = 0; mt < 4; mt++) aRowOff[mt] = (wm * 64 + mt * 16 + aRL) * 128;
#pragma unroll
    for (int nt = 0; nt < 2; nt++) bRowOff[nt] = (wn * 32 + nt * 16 + bRL) * 128;
    unsigned aMsk = aRL & 7, bMsk = bRL & 7;

    float c[16][4];
#pragma unroll
    for (int i = 0; i < 16; i++)
#pragma unroll
        for (int j = 0; j < 4; j++) c[i][j] = 0.f;

    load_chunk(smBase, 0, 0, oBase, pBase, tid);

    for (int ch = 0; ch < NCHUNK; ch++) {
        if (ch + 1 < NCHUNK) {
            load_chunk(smBase, (ch + 1) & 1, ch + 1, oBase, pBase, tid);
            asm volatile("cp.async.wait_group 1;" ::: "memory");
        } else {
            asm volatile("cp.async.wait_group 0;" ::: "memory");
        }
        __syncthreads();

        unsigned base = smBase + (ch & 1) * STAGEB;
        unsigned sAh = base, sAl = base + TILEB, sBh = base + 2 * TILEB, sBl = base + 3 * TILEB;

#pragma unroll
        for (int kk = 0; kk < 4; kk++) {
            unsigned ua = ((kk * 2 + aU) ^ aMsk) * 16;
            unsigned ub = ((kk * 2 + bU) ^ bMsk) * 16;

            unsigned ah[4][4], al[4][4], bh[2][4], bl[2][4];
#pragma unroll
            for (int mt = 0; mt < 4; mt++) {
                LDM4(ah[mt][0], ah[mt][1], ah[mt][2], ah[mt][3], sAh + aRowOff[mt] + ua);
                LDM4(al[mt][0], al[mt][1], al[mt][2], al[mt][3], sAl + aRowOff[mt] + ua);
            }
#pragma unroll
            for (int nt = 0; nt < 2; nt++) {
                LDM4(bh[nt][0], bh[nt][1], bh[nt][2], bh[nt][3], sBh + bRowOff[nt] + ub);
                LDM4(bl[nt][0], bl[nt][1], bl[nt][2], bl[nt][3], sBl + bRowOff[nt] + ub);
            }

#pragma unroll
            for (int mt = 0; mt < 4; mt++)
#pragma unroll
                for (int nt = 0; nt < 4; nt++) {
                    int n2 = nt >> 1, jj = (nt & 1) * 2;
                    float* cc = c[mt * 4 + nt];
                    MMA(cc, ah[mt], bh[n2][jj], bh[n2][jj + 1]);
                    MMA(cc, ah[mt], bl[n2][jj], bl[n2][jj + 1]);
                    MMA(cc, al[mt], bh[n2][jj], bh[n2][jj + 1]);
                }
        }
        __syncthreads();
    }

    // Epilogue: + bias, NCHW stores (pixel tile stays inside one batch image).
    int b = pBase / HW, hwB = pBase % HW;
#pragma unroll
    for (int mt = 0; mt < 4; mt++) {
        int o = oBase + wm * 64 + mt * 16 + (lane >> 2);
        float bias0 = bconv[o], bias8 = bconv[o + 8];
        float* r0p = out + ((size_t)b * CHO + o) * HW + hwB;
        float* r8p = r0p + 8 * HW;
#pragma unroll
        for (int nt = 0; nt < 4; nt++) {
            int p = wn * 32 + nt * 8 + (lane & 3) * 2;
            float2 v0 = make_float2(c[mt * 4 + nt][0] + bias0, c[mt * 4 + nt][1] + bias0);
            float2 v1 = make_float2(c[mt * 4 + nt][2] + bias8, c[mt * 4 + nt][3] + bias8);
            *(float2*)(r0p + p) = v0;
            *(float2*)(r8p + p) = v1;
        }
    }
}

// ---------------------------------------------------------------------------
// Kernel 5/6: BN stats + apply.
// ---------------------------------------------------------------------------
__global__ void __launch_bounds__(256) k_bnstats(const float* __restrict__ out)
{
    __shared__ float ss[256], ss2[256];
    int o = blockIdx.x;
    float s = 0.f, s2 = 0.f;
    for (int i = threadIdx.x; i < Bn * HW; i += 256) {
        int b = i / HW;
        float v = out[((size_t)b * CHO + o) * HW + (i % HW)];
        s += v; s2 += v * v;
    }
    ss[threadIdx.x] = s; ss2[threadIdx.x] = s2;
    __syncthreads();
    for (int st = 128; st > 0; st >>= 1) {
        if (threadIdx.x < st) {
            ss[threadIdx.x]  += ss[threadIdx.x + st];
            ss2[threadIdx.x] += ss2[threadIdx.x + st];
        }
        __syncthreads();
    }
    if (threadIdx.x == 0) {
        float inv_n = 1.f / (float)(Bn * HW);
        float mean = ss[0] * inv_n;
        float var  = ss2[0] * inv_n - mean * mean;
        g_stats[o]       = mean;
        g_stats[CHO + o] = rsqrtf(var + BN_EPS);
    }
}

__global__ void __launch_bounds__(256) k_bnapply(
    float* __restrict__ out,
    const float* __restrict__ gamma,
    const float* __restrict__ beta)
{
    int i = blockIdx.x * 256 + threadIdx.x;
    int o = (i / HW) & (CHO - 1);
    float v = out[i];
    float y = gamma[o] * ((v - g_stats[o]) * g_stats[CHO + o]) + beta[o];
    out[i] = fmaxf(y, 0.f);
}

// ---------------------------------------------------------------------------
extern "C" void kernel_launch(void* const* d_in, const int* in_sizes, int n_in,
                              void* d_out, int out_size)
{
    const float* x      = (const float*)d_in[0];
    const float* w_off  = (const float*)d_in[1];
    const float* b_off  = (const float*)d_in[2];
    const float* w_conv = (const float*)d_in[3];
    const float* b_conv = (const float*)d_in[4];
    const float* gamma  = (const float*)d_in[5];
    const float* beta   = (const float*)d_in[6];
    float* out = (float*)d_out;

    cudaFuncSetAttribute(k_gemm, cudaFuncAttributeMaxDynamicSharedMemorySize,
                         2 * STAGEB);

    k_offset<<<Mpx / 128, 128>>>(x, w_off, b_off);
    k_wsplit<<<(CHO * KD) / 256, 256>>>(w_conv);

    k_cols<<<Mpx / 128, 128>>>(x);

    dim3 ggemm(Mpx / 128, CHO / 128);
    k_gemm<<<ggemm, 256, 2 * STAGEB>>>(b_conv, out);

    k_bnstats<<<CHO, 256>>>(out);
    k_bnapply<<<(size_t)Bn * CHO * HW / 256, 256>>>(out, gamma, beta);
}

// round 10
// speedup vs baseline: 1.5212x; 1.1584x over previous
#include <cuda_runtime.h>
#include <cuda_fp16.h>

// Problem constants
#define Bn   4
#define CHI  256
#define CHO  256
#define Hd   96
#define Wd   96
#define Kt   9
#define HW   (Hd*Wd)          // 9216
#define Mpx  (Bn*HW)          // 36864
#define KD   (CHI*Kt)         // 2304
#define BN_EPS 1e-5f

// Bilinear tap: 4 clamped offsets + 4 corner weights (validity+mask folded in)
struct __align__(16) TapParam {
    int   o00, o01, o10, o11;
    float w00, w01, w10, w11;
};

// Scratch (device globals: allocation-guard-safe)
__device__ TapParam       g_params[Bn * Kt * HW];                       // ~10.6 MB
__device__ __align__(16) unsigned short g_cols[(size_t)Mpx * KD];       // 170 MB fp16
__device__ __align__(16) unsigned short g_wh[(size_t)CHO * KD];         // 1.18 MB
__device__ __align__(16) unsigned short g_wl[(size_t)CHO * KD];
__device__ float          g_stats[2 * CHO];

// ---------------------------------------------------------------------------
// Kernel 1: offset conv (256->27, 3x3, pad 1) -> TapParams.
// 2 pixels per thread: every float4 smem weight load feeds 8 FFMA.
// ---------------------------------------------------------------------------
#define OC  27
#define OCP 32

__global__ void __launch_bounds__(128) k_offset(
    const float* __restrict__ x,
    const float* __restrict__ w_off,
    const float* __restrict__ b_off)
{
    __shared__ float ws[32 * 9 * OCP];
    int p0 = blockIdx.x * 256 + threadIdx.x;       // grid.x = Mpx/256 = 144
    int b  = (blockIdx.x * 256) / HW;              // whole block in one image

    int hw0 = p0 % HW, h0 = hw0 / Wd, w0 = hw0 % Wd;
    int hw1 = (p0 + 128) % HW, h1 = hw1 / Wd, w1 = hw1 % Wd;

    float acc[2][28];
#pragma unroll
    for (int q = 0; q < 2; q++)
#pragma unroll
        for (int i = 0; i < 28; i++) acc[q][i] = 0.f;

    for (int c0 = 0; c0 < CHI; c0 += 32) {
        __syncthreads();
        for (int i = threadIdx.x; i < 32 * 9 * OC; i += 128) {
            int oc = i % OC;
            int ct = i / OC;
            ws[ct * OCP + oc] = w_off[(oc * CHI + c0 + ct / 9) * 9 + (ct % 9)];
        }
        __syncthreads();

        const float* xb = x + ((size_t)b * CHI + c0) * HW;
        for (int cc = 0; cc < 32; cc++) {
            const float* xc = xb + cc * HW;
            float xv0[9], xv1[9];
#pragma unroll
            for (int ty = 0; ty < 3; ty++) {
                int ya = h0 + ty - 1, yb2 = h1 + ty - 1;
                bool yva = ((unsigned)ya < (unsigned)Hd);
                bool yvb = ((unsigned)yb2 < (unsigned)Hd);
#pragma unroll
                for (int tx = 0; tx < 3; tx++) {
                    int xa = w0 + tx - 1, xb2 = w1 + tx - 1;
                    xv0[ty * 3 + tx] = (yva && (unsigned)xa < (unsigned)Wd)
                                     ? xc[ya * Wd + xa] : 0.f;
                    xv1[ty * 3 + tx] = (yvb && (unsigned)xb2 < (unsigned)Wd)
                                     ? xc[yb2 * Wd + xb2] : 0.f;
                }
            }
#pragma unroll
            for (int t = 0; t < 9; t++) {
                const float4* wr4 = (const float4*)&ws[(cc * 9 + t) * OCP];
                float v0 = xv0[t], v1 = xv1[t];
#pragma unroll
                for (int j = 0; j < 7; j++) {
                    float4 w4 = wr4[j];
                    acc[0][j*4+0] += w4.x * v0;  acc[1][j*4+0] += w4.x * v1;
                    acc[0][j*4+1] += w4.y * v0;  acc[1][j*4+1] += w4.y * v1;
                    acc[0][j*4+2] += w4.z * v0;  acc[1][j*4+2] += w4.z * v1;
                    acc[0][j*4+3] += w4.w * v0;  acc[1][j*4+3] += w4.w * v1;
                }
            }
        }
    }

#pragma unroll
    for (int q = 0; q < 2; q++) {
        int hw = (q == 0) ? hw0 : hw1;
        int h  = (q == 0) ? h0  : h1;
        int w  = (q == 0) ? w0  : w1;
#pragma unroll
        for (int k = 0; k < Kt; k++) {
            float dy = acc[q][2 * k]     + b_off[2 * k];
            float dx = acc[q][2 * k + 1] + b_off[2 * k + 1];
            float mz = acc[q][18 + k]    + b_off[18 + k];
            float m  = 1.f / (1.f + expf(-mz));

            float py = dy + (float)(h + k / 3 - 1);
            float px = dx + (float)(w + k % 3 - 1);
            float fy = floorf(py), fx = floorf(px);
            float ly = py - fy,    lx = px - fx;
            int y0 = (int)fy, x0 = (int)fx, y1 = y0 + 1, x1 = x0 + 1;

            float vy0 = ((unsigned)y0 < (unsigned)Hd) ? 1.f : 0.f;
            float vy1 = ((unsigned)y1 < (unsigned)Hd) ? 1.f : 0.f;
            float vx0 = ((unsigned)x0 < (unsigned)Wd) ? 1.f : 0.f;
            float vx1 = ((unsigned)x1 < (unsigned)Wd) ? 1.f : 0.f;

            int y0c = min(max(y0, 0), Hd - 1), y1c = min(max(y1, 0), Hd - 1);
            int x0c = min(max(x0, 0), Wd - 1), x1c = min(max(x1, 0), Wd - 1);

            TapParam tp;
            tp.o00 = y0c * Wd + x0c;  tp.o01 = y0c * Wd + x1c;
            tp.o10 = y1c * Wd + x0c;  tp.o11 = y1c * Wd + x1c;
            tp.w00 = (1.f - ly) * (1.f - lx) * vy0 * vx0 * m;
            tp.w01 = (1.f - ly) * lx         * vy0 * vx1 * m;
            tp.w10 = ly * (1.f - lx)         * vy1 * vx0 * m;
            tp.w11 = ly * lx                 * vy1 * vx1 * m;
            g_params[(b * Kt + k) * HW + hw] = tp;
        }
    }
}

// ---------------------------------------------------------------------------
// Kernel 2: split w_conv into fp16 hi/lo, [CHO][KD] K-major.
// ---------------------------------------------------------------------------
__global__ void __launch_bounds__(256) k_wsplit(const float* __restrict__ w)
{
    int i = blockIdx.x * 256 + threadIdx.x;
    float v = w[i];
    __half hh = __float2half_rn(v);
    float r = v - __half2float(hh);
    __half hl = __float2half_rn(r);
    g_wh[i] = __half_as_ushort(hh);
    g_wl[i] = __half_as_ushort(hl);
}

// ---------------------------------------------------------------------------
// Kernel 3: deformable im2col -> fp16, K-major [pixel][KD].
// Thread = (pixel, 8-channel chunk): wide parallelism (round-4 structure).
// ---------------------------------------------------------------------------
__global__ void __launch_bounds__(256) k_cols(const float* __restrict__ x)
{
    int p  = blockIdx.x * 256 + threadIdx.x;   // grid.x = 144
    int c0 = blockIdx.y * 8;                   // grid.y = 32
    int b  = p / HW, hw = p % HW;
    const float* xb = x + ((size_t)b * CHI + c0) * HW;

    unsigned buf[36];
#pragma unroll
    for (int j = 0; j < 36; j++) buf[j] = 0u;

#pragma unroll
    for (int k = 0; k < Kt; k++) {
        TapParam tp = g_params[(b * Kt + k) * HW + hw];
#pragma unroll
        for (int cc = 0; cc < 8; cc++) {
            const float* xc = xb + cc * HW;
            float v = tp.w00 * __ldg(xc + tp.o00) + tp.w01 * __ldg(xc + tp.o01)
                    + tp.w10 * __ldg(xc + tp.o10) + tp.w11 * __ldg(xc + tp.o11);
            unsigned hb = (unsigned)__half_as_ushort(__float2half_rn(v));
            int e = cc * 9 + k;
            buf[e >> 1] |= hb << ((e & 1) * 16);
        }
    }

    uint4* dh = (uint4*)(g_cols + (size_t)p * KD + c0 * 9);
#pragma unroll
    for (int j = 0; j < 9; j++)
        dh[j] = make_uint4(buf[4*j], buf[4*j+1], buf[4*j+2], buf[4*j+3]);
}

// ---------------------------------------------------------------------------
// Kernel 4: mma.sync fp16 GEMM, split-A 2-product fp32 accumulation.
// CTA: 128 CHO x 128 pixels. 8 warps, warp tile 64x32. BK=64, 3-stage cp.async.
// smem tile: [128 rows][64 fp16] with SW128 row swizzle (u ^= row&7).
// ---------------------------------------------------------------------------
#define NCHUNK 36
#define TILEB  16384                 // 128 rows x 128 bytes
#define STAGEB (3 * TILEB)           // Ahi Alo B
#define NSTAGE 3
#define SMEMSZ (NSTAGE * STAGEB)     // 147456

#define LDM4(R0,R1,R2,R3,ADDR) \
    asm volatile("ldmatrix.sync.aligned.m8n8.x4.shared.b16 {%0,%1,%2,%3}, [%4];" \
                 : "=r"(R0),"=r"(R1),"=r"(R2),"=r"(R3) : "r"(ADDR))

#define MMA(C,A,B0,B1) \
    asm volatile("mma.sync.aligned.m16n8k16.row.col.f32.f16.f16.f32 " \
                 "{%0,%1,%2,%3},{%4,%5,%6,%7},{%8,%9},{%0,%1,%2,%3};" \
                 : "+f"((C)[0]),"+f"((C)[1]),"+f"((C)[2]),"+f"((C)[3]) \
                 : "r"((A)[0]),"r"((A)[1]),"r"((A)[2]),"r"((A)[3]),   \
                   "r"(B0),"r"(B1))

__device__ __forceinline__ void load_chunk(unsigned smBase, int stage, int chunk,
                                           int oBase, int pBase, int tid)
{
    unsigned dstBase = smBase + stage * STAGEB;
    int k0 = chunk * 64;
#pragma unroll
    for (int j = 0; j < 12; j++) {
        int i    = tid + j * 256;        // 0..3071
        int tile = i >> 10;              // 0..2
        int row  = (i >> 3) & 127;
        int u    = i & 7;
        const unsigned short* src;
        int rbase;
        if (tile == 0)      { src = g_wh;   rbase = oBase; }
        else if (tile == 1) { src = g_wl;   rbase = oBase; }
        else                { src = g_cols; rbase = pBase; }
        const char* g = (const char*)src + ((size_t)(rbase + row) * KD + k0) * 2 + u * 16;
        unsigned d = dstBase + tile * TILEB + row * 128 + ((u ^ (row & 7)) * 16);
        asm volatile("cp.async.cg.shared.global [%0], [%1], 16;" :: "r"(d), "l"(g));
    }
    asm volatile("cp.async.commit_group;" ::: "memory");
}

__global__ void __launch_bounds__(256, 1) k_gemm(
    const float* __restrict__ bconv,
    float* __restrict__ out)
{
    extern __shared__ char sm[];
    unsigned smBase = (unsigned)__cvta_generic_to_shared(sm);

    int tid = threadIdx.x, lane = tid & 31, wid = tid >> 5;
    int wm = wid & 1;            // m half (64 rows)
    int wn = wid >> 1;           // n quarter (32 pixels)
    int pBase = blockIdx.x * 128;
    int oBase = blockIdx.y * 128;

    // ldmatrix per-lane geometry
    unsigned aRL = ((lane >> 3) & 1) * 8 + (lane & 7);   // A: row-in-tile16
    unsigned aU  = lane >> 4;                            // A: k8 unit
    unsigned bRL = ((lane >> 4) & 1) * 8 + (lane & 7);   // B: row-in-tile16
    unsigned bU  = (lane >> 3) & 1;                      // B: k8 unit
    unsigned aRowOff[4], bRowOff[2];
#pragma unroll
    for (int mt = 0; mt < 4; mt++) aRowOff[mt] = (wm * 64 + mt * 16 + aRL) * 128;
#pragma unroll
    for (int nt = 0; nt < 2; nt++) bRowOff[nt] = (wn * 32 + nt * 16 + bRL) * 128;
    unsigned aMsk = aRL & 7, bMsk = bRL & 7;

    float c[16][4];
#pragma unroll
    for (int i = 0; i < 16; i++)
#pragma unroll
        for (int j = 0; j < 4; j++) c[i][j] = 0.f;

    load_chunk(smBase, 0, 0, oBase, pBase, tid);
    load_chunk(smBase, 1, 1, oBase, pBase, tid);

    for (int ch = 0; ch < NCHUNK; ch++) {
        int st = ch % NSTAGE;
        if (ch + 2 < NCHUNK) {
            load_chunk(smBase, (ch + 2) % NSTAGE, ch + 2, oBase, pBase, tid);
            asm volatile("cp.async.wait_group 2;" ::: "memory");
        } else if (ch + 1 < NCHUNK) {
            asm volatile("cp.async.wait_group 1;" ::: "memory");
        } else {
            asm volatile("cp.async.wait_group 0;" ::: "memory");
        }
        __syncthreads();

        unsigned base = smBase + st * STAGEB;
        unsigned sAh = base, sAl = base + TILEB, sB = base + 2 * TILEB;

#pragma unroll
        for (int kk = 0; kk < 4; kk++) {
            unsigned ua = ((kk * 2 + aU) ^ aMsk) * 16;
            unsigned ub = ((kk * 2 + bU) ^ bMsk) * 16;

            unsigned ah[4][4], al[4][4], bh[2][4];
#pragma unroll
            for (int mt = 0; mt < 4; mt++) {
                LDM4(ah[mt][0], ah[mt][1], ah[mt][2], ah[mt][3], sAh + aRowOff[mt] + ua);
                LDM4(al[mt][0], al[mt][1], al[mt][2], al[mt][3], sAl + aRowOff[mt] + ua);
            }
#pragma unroll
            for (int nt = 0; nt < 2; nt++)
                LDM4(bh[nt][0], bh[nt][1], bh[nt][2], bh[nt][3], sB + bRowOff[nt] + ub);

#pragma unroll
            for (int mt = 0; mt < 4; mt++)
#pragma unroll
                for (int nt = 0; nt < 4; nt++) {
                    int n2 = nt >> 1, jj = (nt & 1) * 2;
                    float* cc = c[mt * 4 + nt];
                    MMA(cc, ah[mt], bh[n2][jj], bh[n2][jj + 1]);
                    MMA(cc, al[mt], bh[n2][jj], bh[n2][jj + 1]);
                }
        }
        __syncthreads();
    }

    // Epilogue: + bias, NCHW stores (pixel tile stays inside one batch image).
    int b = pBase / HW, hwB = pBase % HW;
#pragma unroll
    for (int mt = 0; mt < 4; mt++) {
        int o = oBase + wm * 64 + mt * 16 + (lane >> 2);
        float bias0 = bconv[o], bias8 = bconv[o + 8];
        float* r0p = out + ((size_t)b * CHO + o) * HW + hwB;
        float* r8p = r0p + 8 * HW;
#pragma unroll
        for (int nt = 0; nt < 4; nt++) {
            int p = wn * 32 + nt * 8 + (lane & 3) * 2;
            float2 v0 = make_float2(c[mt * 4 + nt][0] + bias0, c[mt * 4 + nt][1] + bias0);
            float2 v1 = make_float2(c[mt * 4 + nt][2] + bias8, c[mt * 4 + nt][3] + bias8);
            *(float2*)(r0p + p) = v0;
            *(float2*)(r8p + p) = v1;
        }
    }
}

// ---------------------------------------------------------------------------
// Kernel 5/6: BN stats + apply.
// ---------------------------------------------------------------------------
__global__ void __launch_bounds__(256) k_bnstats(const float* __restrict__ out)
{
    __shared__ float ss[256], ss2[256];
    int o = blockIdx.x;
    float s = 0.f, s2 = 0.f;
    for (int i = threadIdx.x; i < Bn * HW; i += 256) {
        int b = i / HW;
        float v = out[((size_t)b * CHO + o) * HW + (i % HW)];
        s += v; s2 += v * v;
    }
    ss[threadIdx.x] = s; ss2[threadIdx.x] = s2;
    __syncthreads();
    for (int st = 128; st > 0; st >>= 1) {
        if (threadIdx.x < st) {
            ss[threadIdx.x]  += ss[threadIdx.x + st];
            ss2[threadIdx.x] += ss2[threadIdx.x + st];
        }
        __syncthreads();
    }
    if (threadIdx.x == 0) {
        float inv_n = 1.f / (float)(Bn * HW);
        float mean = ss[0] * inv_n;
        float var  = ss2[0] * inv_n - mean * mean;
        g_stats[o]       = mean;
        g_stats[CHO + o] = rsqrtf(var + BN_EPS);
    }
}

__global__ void __launch_bounds__(256) k_bnapply(
    float* __restrict__ out,
    const float* __restrict__ gamma,
    const float* __restrict__ beta)
{
    int i = blockIdx.x * 256 + threadIdx.x;
    int o = (i / HW) & (CHO - 1);
    float v = out[i];
    float y = gamma[o] * ((v - g_stats[o]) * g_stats[CHO + o]) + beta[o];
    out[i] = fmaxf(y, 0.f);
}

// ---------------------------------------------------------------------------
extern "C" void kernel_launch(void* const* d_in, const int* in_sizes, int n_in,
                              void* d_out, int out_size)
{
    const float* x      = (const float*)d_in[0];
    const float* w_off  = (const float*)d_in[1];
    const float* b_off  = (const float*)d_in[2];
    const float* w_conv = (const float*)d_in[3];
    const float* b_conv = (const float*)d_in[4];
    const float* gamma  = (const float*)d_in[5];
    const float* beta   = (const float*)d_in[6];
    float* out = (float*)d_out;

    cudaFuncSetAttribute(k_gemm, cudaFuncAttributeMaxDynamicSharedMemorySize,
                         SMEMSZ);

    k_offset<<<Mpx / 256, 128>>>(x, w_off, b_off);
    k_wsplit<<<(CHO * KD) / 256, 256>>>(w_conv);

    dim3 gcols(Mpx / 256, CHI / 8);
    k_cols<<<gcols, 256>>>(x);

    dim3 ggemm(Mpx / 128, CHO / 128);
    k_gemm<<<ggemm, 256, SMEMSZ>>>(b_conv, out);

    k_bnstats<<<CHO, 256>>>(out);
    k_bnapply<<<(size_t)Bn * CHO * HW / 256, 256>>>(out, gamma, beta);
}